// round 12
// baseline (speedup 1.0000x reference)
#include <cuda_runtime.h>
#include <cuda_bf16.h>
#include <math.h>
#include <stdint.h>

#define N_NODES 30000
#define N_EDGES 480000
#define B_PAIRS 4096
#define CDIV(a,b) (((a)+(b)-1)/(b))

// ---------------- scratch (static device memory; no allocations) ----------------
__device__ float g_x881[N_NODES * 881];
__device__ float g_h[N_NODES * 256];
__device__ float g_t[N_NODES * 256];
__device__ float g_dinv[N_NODES];
__device__ int   g_cnt[N_NODES];
__device__ int   g_fill[N_NODES];
__device__ int   g_rowptr[N_NODES + 1];
__device__ int   g_col[N_EDGES];
__device__ float g_w[N_EDGES];
__device__ float g_xc[B_PAIRS * 256];
__device__ float g_p1[B_PAIRS * 1024];
__device__ float g_p3[B_PAIRS * 64];
__device__ int   g_is64;

// pre-split weights (bf16 hi/lo), padded N stride where needed
__device__ __align__(16) __nv_bfloat16 g_whi[1800000];
__device__ __align__(16) __nv_bfloat16 g_wlo[1800000];
// offsets (elements); every length is a multiple of 8 so 16B alignment holds
#define O_W2 0          // 881 x 888 (padded from 881)
#define O_W3 782328     // 881 x 256
#define O_G1 1007864    // 256 x 256
#define O_G2 1073400
#define O_G3 1138936
#define O_G4 1204472    // 256 x 128
#define O_G5 1237240    // 128 x 128
#define O_F1 1253624    // 256 x 1024
#define O_F2 1515768    // 1024 x 256
#define O_F3 1777912    // 256 x 64

// ---------------- weight split: fp32 [K][N] -> bf16 hi/lo [K][Npad] ----------------
__global__ void k_split(const float* __restrict__ src, int K, int N, int Npad, int off) {
    int idx = blockIdx.x * blockDim.x + threadIdx.x;
    if (idx >= K * Npad) return;
    int r = idx / Npad, c = idx % Npad;
    float v = (c < N) ? src[(size_t)r * N + c] : 0.f;
    __nv_bfloat16 h = __float2bfloat16(v);
    __nv_bfloat16 l = __float2bfloat16(v - __bfloat162float(h));
    g_whi[off + idx] = h;
    g_wlo[off + idx] = l;
}

// ---------------- fused init: zero counters + detect index dtype ----------------
__global__ void k_init(const unsigned int* p) {
    int i = blockIdx.x * blockDim.x + threadIdx.x;
    if (i < N_NODES) { g_cnt[i] = 0; g_fill[i] = 0; }
    if (blockIdx.x == 0) {
        __shared__ int any;
        if (threadIdx.x == 0) any = 0;
        __syncthreads();
        int loc = 0;
        for (int j = threadIdx.x; j < 2048; j += blockDim.x)
            if (p[2 * j + 1] != 0u) loc = 1;
        if (loc) any = 1;
        __syncthreads();
        if (threadIdx.x == 0) g_is64 = (any == 0);
    }
}

__device__ __forceinline__ int ld_idx(const void* p, long long i) {
    if (g_is64) return (int)((const long long*)p)[i];
    return ((const int*)p)[i];
}

// ---------------- graph preprocessing ----------------
__global__ void k_count(const void* edges) {
    int e = blockIdx.x * blockDim.x + threadIdx.x;
    if (e >= N_EDGES) return;
    int d = ld_idx(edges, (long long)N_EDGES + e);
    atomicAdd(&g_cnt[d], 1);
}

__global__ void k_dinv() {
    int i = blockIdx.x * blockDim.x + threadIdx.x;
    if (i < N_NODES) g_dinv[i] = rsqrtf((float)(g_cnt[i] + 1));
}

__global__ void k_scan() {
    __shared__ int s[1024];
    __shared__ int carry;
    int t = threadIdx.x;
    if (t == 0) { carry = 0; g_rowptr[0] = 0; }
    __syncthreads();
    for (int base = 0; base < N_NODES; base += 1024) {
        int i = base + t;
        int v = (i < N_NODES) ? g_cnt[i] : 0;
        s[t] = v;
        __syncthreads();
        for (int off = 1; off < 1024; off <<= 1) {
            int add = (t >= off) ? s[t - off] : 0;
            __syncthreads();
            s[t] += add;
            __syncthreads();
        }
        if (i < N_NODES) g_rowptr[i + 1] = carry + s[t];
        __syncthreads();
        if (t == 0) carry += s[1023];
        __syncthreads();
    }
}

__global__ void k_fill(const void* edges) {
    int e = blockIdx.x * blockDim.x + threadIdx.x;
    if (e >= N_EDGES) return;
    int s = ld_idx(edges, e);
    int d = ld_idx(edges, (long long)N_EDGES + e);
    int pos = g_rowptr[d] + atomicAdd(&g_fill[d], 1);
    g_col[pos] = s;
    g_w[pos] = g_dinv[s] * g_dinv[d];
}

// =====================================================================
// bf16-split tensor GEMM: C = epi(A[M,K] @ B[K,N] + bias)
// A fp32 split on the fly; B pre-split (bf16 hi/lo, stride Nb) via cp.async.
// Block 128x128, 4 warps (2m x 2n), warp tile 64x64, BK=16, double buffered.
// EPI 0: none  1: relu  2: relu+soft-threshold
// =====================================================================
#define MMA_BF16(d, a0, a1, a2, a3, b0, b1) \
    asm volatile("mma.sync.aligned.m16n8k16.row.col.f32.bf16.bf16.f32 " \
                 "{%0,%1,%2,%3},{%4,%5,%6,%7},{%8,%9},{%0,%1,%2,%3};" \
                 : "+f"(d[0]), "+f"(d[1]), "+f"(d[2]), "+f"(d[3]) \
                 : "r"(a0), "r"(a1), "r"(a2), "r"(a3), "r"(b0), "r"(b1))

__device__ __forceinline__ void ldsm_x4(uint32_t& r0, uint32_t& r1, uint32_t& r2,
                                        uint32_t& r3, uint32_t addr) {
    asm volatile("ldmatrix.sync.aligned.m8n8.x4.shared.b16 {%0,%1,%2,%3},[%4];"
                 : "=r"(r0), "=r"(r1), "=r"(r2), "=r"(r3) : "r"(addr));
}
__device__ __forceinline__ void ldsm_x4_t(uint32_t& r0, uint32_t& r1, uint32_t& r2,
                                          uint32_t& r3, uint32_t addr) {
    asm volatile("ldmatrix.sync.aligned.m8n8.x4.trans.shared.b16 {%0,%1,%2,%3},[%4];"
                 : "=r"(r0), "=r"(r1), "=r"(r2), "=r"(r3) : "r"(addr));
}
__device__ __forceinline__ void cp16(uint32_t dst, const void* src, int bytes) {
    asm volatile("cp.async.cg.shared.global [%0], [%1], 16, %2;"
                 :: "r"(dst), "l"(src), "r"(bytes));
}
#define CP_COMMIT() asm volatile("cp.async.commit_group;" ::: "memory")
#define CP_WAIT0()  asm volatile("cp.async.wait_group 0;" ::: "memory")

template <int EPI>
__global__ __launch_bounds__(128, 2) void k_tgemm(
    const float* __restrict__ A,
    const __nv_bfloat16* __restrict__ Bhi, const __nv_bfloat16* __restrict__ Blo,
    int Nb,   // padded stride of Bhi/Blo
    const float* __restrict__ bias, float* __restrict__ C,
    int M, int K, int N, const float* __restrict__ thrp)
{
    const int PA = 24;    // A pitch (bf16)
    const int PBN = 136;  // B pitch (bf16)
    __shared__ __align__(16) __nv_bfloat16 As_hi[2][128][PA];
    __shared__ __align__(16) __nv_bfloat16 As_lo[2][128][PA];
    __shared__ __align__(16) __nv_bfloat16 Bs_hi[2][16][PBN];
    __shared__ __align__(16) __nv_bfloat16 Bs_lo[2][16][PBN];

    int tid = threadIdx.x;
    int lane = tid & 31, warp = tid >> 5;   // 4 warps
    int wm = warp >> 1;        // 0..1  (64 rows)
    int wn = warp & 1;         // 0..1  (64 cols)
    int fr = lane >> 2;        // 0..7
    int fc = lane & 3;         // 0..3
    int m0 = blockIdx.y * 128, n0 = blockIdx.x * 128;

    // A loader: thread -> row tid (0..127), all 16 k
    int arow = tid;

    // ldmatrix lane addressing (same mapping as passing R10 kernel)
    int a_r = (lane & 15);
    int a_c = (lane >> 4) * 8;
    int b_k = (lane & 7) + ((lane >> 3) & 1) * 8;
    int b_c = (lane >> 4) * 8;

    uint32_t sAhi = (uint32_t)__cvta_generic_to_shared(&As_hi[0][0][0]);
    uint32_t sAlo = (uint32_t)__cvta_generic_to_shared(&As_lo[0][0][0]);
    uint32_t sBhi = (uint32_t)__cvta_generic_to_shared(&Bs_hi[0][0][0]);
    uint32_t sBlo = (uint32_t)__cvta_generic_to_shared(&Bs_lo[0][0][0]);

    float acc[4][8][4];
#pragma unroll
    for (int mi = 0; mi < 4; mi++)
#pragma unroll
        for (int ni = 0; ni < 8; ni++)
#pragma unroll
            for (int q = 0; q < 4; q++) acc[mi][ni][q] = 0.f;

    float fa[16];
    int nch = CDIV(K, 16);

#define LDG_CHUNK(kc) do { \
    int k0_ = (kc) * 16; \
    long long ar_ = m0 + arow; \
    const float* pA_ = A + (size_t)ar_ * K + k0_; \
    bool rok_ = ar_ < M; \
    _Pragma("unroll") \
    for (int j = 0; j < 16; j++) { \
        int k_ = k0_ + j; \
        fa[j] = (rok_ && k_ < K) ? pA_[j] : 0.f; \
    } \
} while (0)

// cp.async B chunk kc into buffer b (hi + lo). 128 thr x 2 slots of 16B per array.
#define CPB_CHUNK(kc, b) do { \
    int k0_ = (kc) * 16; \
    _Pragma("unroll") \
    for (int i2 = 0; i2 < 2; i2++) { \
        int s_ = tid * 2 + i2; \
        int kr_ = s_ >> 4, nc_ = (s_ & 15) * 8; \
        int kg_ = k0_ + kr_; \
        int rem_ = (Nb - (n0 + nc_)) * 2; \
        int val_ = (kg_ < K) ? (rem_ < 0 ? 0 : (rem_ > 16 ? 16 : rem_)) : 0; \
        size_t go_ = (size_t)kg_ * Nb + n0 + nc_; \
        uint32_t so_ = (uint32_t)((((b) * 16 + kr_) * PBN + nc_) * 2); \
        cp16(sBhi + so_, Bhi + go_, val_); \
        cp16(sBlo + so_, Blo + go_, val_); \
    } \
} while (0)

#define STS_CHUNK(b) do { \
    _Pragma("unroll") \
    for (int i = 0; i < 8; i++) { \
        float v0_ = fa[2 * i], v1_ = fa[2 * i + 1]; \
        __nv_bfloat16 h0_ = __float2bfloat16(v0_); \
        __nv_bfloat16 h1_ = __float2bfloat16(v1_); \
        __nv_bfloat16 l0_ = __float2bfloat16(v0_ - __bfloat162float(h0_)); \
        __nv_bfloat16 l1_ = __float2bfloat16(v1_ - __bfloat162float(h1_)); \
        __nv_bfloat162 hh_; hh_.x = h0_; hh_.y = h1_; \
        __nv_bfloat162 ll_; ll_.x = l0_; ll_.y = l1_; \
        *(__nv_bfloat162*)&As_hi[b][arow][2 * i] = hh_; \
        *(__nv_bfloat162*)&As_lo[b][arow][2 * i] = ll_; \
    } \
} while (0)

    // prologue
    CPB_CHUNK(0, 0);
    CP_COMMIT();
    LDG_CHUNK(0);
    STS_CHUNK(0);
    CP_WAIT0();
    __syncthreads();

    int buf = 0;
    for (int ch = 0; ch < nch; ch++) {
        bool more = (ch + 1) < nch;
        if (more) {
            LDG_CHUNK(ch + 1);
            CPB_CHUNK(ch + 1, buf ^ 1);
            CP_COMMIT();
        }

        // A fragments (hi+lo): 8 LDSM.x4 per warp
        uint32_t ah[4][4], al[4][4];
#pragma unroll
        for (int mi = 0; mi < 4; mi++) {
            uint32_t off = (uint32_t)(((buf * 128 + wm * 64 + mi * 16 + a_r) * PA + a_c) * 2);
            ldsm_x4(ah[mi][0], ah[mi][1], ah[mi][2], ah[mi][3], sAhi + off);
            ldsm_x4(al[mi][0], al[mi][1], al[mi][2], al[mi][3], sAlo + off);
        }
        // B fragments: 4 pairs of 16 cols each (warp covers 64 cols)
#pragma unroll
        for (int p = 0; p < 4; p++) {
            int c0 = wn * 64 + p * 16;
            uint32_t off = (uint32_t)(((buf * 16 + b_k) * PBN + c0 + b_c) * 2);
            uint32_t bh0, bh1, bh2, bh3, bl0, bl1, bl2, bl3;
            ldsm_x4_t(bh0, bh1, bh2, bh3, sBhi + off);
            ldsm_x4_t(bl0, bl1, bl2, bl3, sBlo + off);
#pragma unroll
            for (int mi = 0; mi < 4; mi++) {
                MMA_BF16(acc[mi][2 * p], ah[mi][0], ah[mi][1], ah[mi][2], ah[mi][3], bh0, bh1);
                MMA_BF16(acc[mi][2 * p], ah[mi][0], ah[mi][1], ah[mi][2], ah[mi][3], bl0, bl1);
                MMA_BF16(acc[mi][2 * p], al[mi][0], al[mi][1], al[mi][2], al[mi][3], bh0, bh1);
                MMA_BF16(acc[mi][2 * p + 1], ah[mi][0], ah[mi][1], ah[mi][2], ah[mi][3], bh2, bh3);
                MMA_BF16(acc[mi][2 * p + 1], ah[mi][0], ah[mi][1], ah[mi][2], ah[mi][3], bl2, bl3);
                MMA_BF16(acc[mi][2 * p + 1], al[mi][0], al[mi][1], al[mi][2], al[mi][3], bh2, bh3);
            }
        }

        if (more) STS_CHUNK(buf ^ 1);
        CP_WAIT0();
        __syncthreads();
        buf ^= 1;
    }

    float thr = (EPI == 2) ? *thrp : 0.f;
#pragma unroll
    for (int mi = 0; mi < 4; mi++) {
#pragma unroll
        for (int ni = 0; ni < 8; ni++) {
            int r0 = m0 + wm * 64 + mi * 16 + fr;
            int c0 = n0 + wn * 64 + ni * 8 + fc * 2;
#pragma unroll
            for (int q = 0; q < 4; q++) {
                int r = r0 + (q >> 1) * 8;
                int c = c0 + (q & 1);
                if (r < M && c < N) {
                    float z = acc[mi][ni][q];
                    if (bias) z += bias[c];
                    if (EPI == 1) z = fmaxf(z, 0.f);
                    if (EPI == 2) z = fmaxf(z - thr, 0.f);
                    C[(size_t)r * N + c] = z;
                }
            }
        }
    }
#undef LDG_CHUNK
#undef CPB_CHUNK
#undef STS_CHUNK
}

// ---------------- GCN aggregation ----------------
template <int F>
__global__ void k_agg(const float* __restrict__ t, const float* __restrict__ bias,
                      float* __restrict__ h)
{
    int node = blockIdx.x;
    int f = threadIdx.x;
    float di = g_dinv[node];
    float acc = di * di * t[(size_t)node * F + f];
    int beg = g_rowptr[node], end = g_rowptr[node + 1];
    __shared__ int scol[128];
    __shared__ float sw[128];
    for (int base = beg; base < end; base += 128) {
        int nchunk = min(128, end - base);
        __syncthreads();
        if (f < nchunk) { scol[f] = g_col[base + f]; sw[f] = g_w[base + f]; }
        __syncthreads();
        for (int j = 0; j < nchunk; j++)
            acc += sw[j] * t[(size_t)scol[j] * F + f];
    }
    float z = acc + bias[f];
    h[(size_t)node * F + f] = (z > 0.f) ? z : expm1f(z);
}

// ---------------- pair gather + L2 normalize ----------------
__global__ void k_pairs(const float* __restrict__ h, const void* i1, const void* i2) {
    int b = blockIdx.x;
    int k = threadIdx.x;  // 128
    int a1 = ld_idx(i1, b), a2 = ld_idx(i2, b);
    float v1 = h[(size_t)a1 * 128 + k];
    float v2 = h[(size_t)a2 * 128 + k];
    float s = v1 * v1 + v2 * v2;
    __shared__ float red[4];
#pragma unroll
    for (int o = 16; o; o >>= 1) s += __shfl_down_sync(0xffffffffu, s, o);
    if ((k & 31) == 0) red[k >> 5] = s;
    __syncthreads();
    float tot = red[0] + red[1] + red[2] + red[3];
    float nrm = fmaxf(sqrtf(tot), 1e-12f);
    float inv = 1.f / nrm;
    g_xc[(size_t)b * 256 + k] = v1 * inv;
    g_xc[(size_t)b * 256 + 128 + k] = v2 * inv;
}

// ---------------- final 64->2 linear ----------------
__global__ void k_out(const float* __restrict__ W, const float* __restrict__ bias,
                      float* __restrict__ out) {
    int b = blockIdx.x;
    int lane = threadIdx.x;  // 32
    float a0 = 0.f, a1 = 0.f;
    for (int k = lane; k < 64; k += 32) {
        float v = g_p3[(size_t)b * 64 + k];
        a0 += v * W[k * 2 + 0];
        a1 += v * W[k * 2 + 1];
    }
#pragma unroll
    for (int o = 16; o; o >>= 1) {
        a0 += __shfl_down_sync(0xffffffffu, a0, o);
        a1 += __shfl_down_sync(0xffffffffu, a1, o);
    }
    if (lane == 0) {
        out[b * 2 + 0] = a0 + bias[0];
        out[b * 2 + 1] = a1 + bias[1];
    }
}

// ---------------- launch ----------------
extern "C" void kernel_launch(void* const* d_in, const int* in_sizes, int n_in,
                              void* d_out, int out_size)
{
    const float* cid   = (const float*)d_in[0];
    const void*  edges = d_in[1];
    const void*  i1    = d_in[2];
    const void*  i2    = d_in[3];
    const float* thr   = (const float*)d_in[4];
    const float* bbW2  = (const float*)d_in[5];
    const float* bbb2  = (const float*)d_in[6];
    const float* bbW3  = (const float*)d_in[7];
    const float* bbb3  = (const float*)d_in[8];
    const float* gW[5] = {(const float*)d_in[9],  (const float*)d_in[11],
                          (const float*)d_in[13], (const float*)d_in[15],
                          (const float*)d_in[17]};
    const float* gb[5] = {(const float*)d_in[10], (const float*)d_in[12],
                          (const float*)d_in[14], (const float*)d_in[16],
                          (const float*)d_in[18]};
    const float* fc1W = (const float*)d_in[19];
    const float* fc1b = (const float*)d_in[20];
    const float* fc2W = (const float*)d_in[21];
    const float* fc2b = (const float*)d_in[22];
    const float* fc3W = (const float*)d_in[23];
    const float* fc3b = (const float*)d_in[24];
    const float* oW   = (const float*)d_in[25];
    const float* ob   = (const float*)d_in[26];
    float* out = (float*)d_out;

    float *x881, *h, *t, *xc, *p1, *p3;
    cudaGetSymbolAddress((void**)&x881, g_x881);
    cudaGetSymbolAddress((void**)&h,    g_h);
    cudaGetSymbolAddress((void**)&t,    g_t);
    cudaGetSymbolAddress((void**)&xc,   g_xc);
    cudaGetSymbolAddress((void**)&p1,   g_p1);
    cudaGetSymbolAddress((void**)&p3,   g_p3);
    __nv_bfloat16 *whi, *wlo;
    cudaGetSymbolAddress((void**)&whi, g_whi);
    cudaGetSymbolAddress((void**)&wlo, g_wlo);

    // split W2 first, keep big GEMM at profiled launch slot #4
    k_split<<<CDIV(881 * 888, 256), 256>>>(bbW2, 881, 881, 888, O_W2);
    k_init<<<CDIV(N_NODES, 256), 256>>>((const unsigned int*)edges);
    k_count<<<CDIV(N_EDGES, 256), 256>>>(edges);
    k_tgemm<2><<<dim3(CDIV(881, 128), CDIV(N_NODES, 128)), 128>>>(
        cid, whi + O_W2, wlo + O_W2, 888, bbb2, x881, N_NODES, 881, 881, thr);
    k_dinv<<<CDIV(N_NODES, 256), 256>>>();
    k_scan<<<1, 1024>>>();
    k_fill<<<CDIV(N_EDGES, 256), 256>>>(edges);

    // split remaining weights
    k_split<<<CDIV(881 * 256, 256), 256>>>(bbW3, 881, 256, 256, O_W3);
    k_split<<<CDIV(256 * 256, 256), 256>>>(gW[0], 256, 256, 256, O_G1);
    k_split<<<CDIV(256 * 256, 256), 256>>>(gW[1], 256, 256, 256, O_G2);
    k_split<<<CDIV(256 * 256, 256), 256>>>(gW[2], 256, 256, 256, O_G3);
    k_split<<<CDIV(256 * 128, 256), 256>>>(gW[3], 256, 128, 128, O_G4);
    k_split<<<CDIV(128 * 128, 256), 256>>>(gW[4], 128, 128, 128, O_G5);
    k_split<<<CDIV(256 * 1024, 256), 256>>>(fc1W, 256, 1024, 1024, O_F1);
    k_split<<<CDIV(1024 * 256, 256), 256>>>(fc2W, 1024, 256, 256, O_F2);
    k_split<<<CDIV(256 * 64, 256), 256>>>(fc3W, 256, 64, 64, O_F3);

    k_tgemm<1><<<dim3(CDIV(256, 128), CDIV(N_NODES, 128)), 128>>>(
        x881, whi + O_W3, wlo + O_W3, 256, bbb3, h, N_NODES, 881, 256, nullptr);

    // 5 GCN layers
    const int fin[5]  = {256, 256, 256, 256, 128};
    const int fout[5] = {256, 256, 256, 128, 128};
    const int goff[5] = {O_G1, O_G2, O_G3, O_G4, O_G5};
    for (int l = 0; l < 5; l++) {
        k_tgemm<0><<<dim3(CDIV(fout[l], 128), CDIV(N_NODES, 128)), 128>>>(
            h, whi + goff[l], wlo + goff[l], fout[l], nullptr, t,
            N_NODES, fin[l], fout[l], nullptr);
        if (fout[l] == 256)
            k_agg<256><<<N_NODES, 256>>>(t, gb[l], h);
        else
            k_agg<128><<<N_NODES, 128>>>(t, gb[l], h);
    }

    // pair readout
    k_pairs<<<B_PAIRS, 128>>>(h, i1, i2);
    k_tgemm<1><<<dim3(CDIV(1024, 128), CDIV(B_PAIRS, 128)), 128>>>(
        xc, whi + O_F1, wlo + O_F1, 1024, fc1b, p1, B_PAIRS, 256, 1024, nullptr);
    k_tgemm<1><<<dim3(CDIV(256, 128), CDIV(B_PAIRS, 128)), 128>>>(
        p1, whi + O_F2, wlo + O_F2, 256, fc2b, xc, B_PAIRS, 1024, 256, nullptr);
    k_tgemm<1><<<dim3(CDIV(64, 128), CDIV(B_PAIRS, 128)), 128>>>(
        xc, whi + O_F3, wlo + O_F3, 64, fc3b, p3, B_PAIRS, 256, 64, nullptr);
    k_out<<<B_PAIRS, 32>>>(oW, ob, out);
}

// round 14
// speedup vs baseline: 1.1486x; 1.1486x over previous
#include <cuda_runtime.h>
#include <cuda_bf16.h>
#include <math.h>
#include <stdint.h>

#define N_NODES 30000
#define N_EDGES 480000
#define B_PAIRS 4096
#define CDIV(a,b) (((a)+(b)-1)/(b))

// ---------------- scratch (static device memory; no allocations) ----------------
__device__ float g_x881[N_NODES * 881];
__device__ float g_h[N_NODES * 256];
__device__ float g_t[N_NODES * 256];
__device__ float g_dinv[N_NODES];
__device__ int   g_cnt[N_NODES];
__device__ int   g_fill[N_NODES];
__device__ int   g_rowptr[N_NODES + 1];
__device__ int   g_col[N_EDGES];
__device__ float g_w[N_EDGES];
__device__ float g_xc[B_PAIRS * 256];
__device__ float g_p1[B_PAIRS * 1024];
__device__ float g_p3[B_PAIRS * 64];
__device__ int   g_is64;

// pre-split weights (bf16 hi/lo), padded N stride where needed
__device__ __align__(16) __nv_bfloat16 g_whi[1800000];
__device__ __align__(16) __nv_bfloat16 g_wlo[1800000];
#define O_W2 0          // 881 x 888 (padded from 881)
#define O_W3 782328     // 881 x 256
#define O_G1 1007864    // 256 x 256
#define O_G2 1073400
#define O_G3 1138936
#define O_G4 1204472    // 256 x 128
#define O_G5 1237240    // 128 x 128
#define O_F1 1253624    // 256 x 1024
#define O_F2 1515768    // 1024 x 256
#define O_F3 1777912    // 256 x 64

// ---------------- weight split: fp32 [K][N] -> bf16 hi/lo [K][Npad] ----------------
__global__ void k_split(const float* __restrict__ src, int K, int N, int Npad, int off) {
    int idx = blockIdx.x * blockDim.x + threadIdx.x;
    if (idx >= K * Npad) return;
    int r = idx / Npad, c = idx % Npad;
    float v = (c < N) ? src[(size_t)r * N + c] : 0.f;
    __nv_bfloat16 h = __float2bfloat16(v);
    __nv_bfloat16 l = __float2bfloat16(v - __bfloat162float(h));
    g_whi[off + idx] = h;
    g_wlo[off + idx] = l;
}

// ---------------- fused init: zero counters + detect index dtype ----------------
__global__ void k_init(const unsigned int* p) {
    int i = blockIdx.x * blockDim.x + threadIdx.x;
    if (i < N_NODES) { g_cnt[i] = 0; g_fill[i] = 0; }
    if (blockIdx.x == 0) {
        __shared__ int any;
        if (threadIdx.x == 0) any = 0;
        __syncthreads();
        int loc = 0;
        for (int j = threadIdx.x; j < 2048; j += blockDim.x)
            if (p[2 * j + 1] != 0u) loc = 1;
        if (loc) any = 1;
        __syncthreads();
        if (threadIdx.x == 0) g_is64 = (any == 0);
    }
}

__device__ __forceinline__ int ld_idx(const void* p, long long i) {
    if (g_is64) return (int)((const long long*)p)[i];
    return ((const int*)p)[i];
}

// ---------------- graph preprocessing ----------------
__global__ void k_count(const void* edges) {
    int e = blockIdx.x * blockDim.x + threadIdx.x;
    if (e >= N_EDGES) return;
    int d = ld_idx(edges, (long long)N_EDGES + e);
    atomicAdd(&g_cnt[d], 1);
}

__global__ void k_dinv() {
    int i = blockIdx.x * blockDim.x + threadIdx.x;
    if (i < N_NODES) g_dinv[i] = rsqrtf((float)(g_cnt[i] + 1));
}

__global__ void k_scan() {
    __shared__ int s[1024];
    __shared__ int carry;
    int t = threadIdx.x;
    if (t == 0) { carry = 0; g_rowptr[0] = 0; }
    __syncthreads();
    for (int base = 0; base < N_NODES; base += 1024) {
        int i = base + t;
        int v = (i < N_NODES) ? g_cnt[i] : 0;
        s[t] = v;
        __syncthreads();
        for (int off = 1; off < 1024; off <<= 1) {
            int add = (t >= off) ? s[t - off] : 0;
            __syncthreads();
            s[t] += add;
            __syncthreads();
        }
        if (i < N_NODES) g_rowptr[i + 1] = carry + s[t];
        __syncthreads();
        if (t == 0) carry += s[1023];
        __syncthreads();
    }
}

__global__ void k_fill(const void* edges) {
    int e = blockIdx.x * blockDim.x + threadIdx.x;
    if (e >= N_EDGES) return;
    int s = ld_idx(edges, e);
    int d = ld_idx(edges, (long long)N_EDGES + e);
    int pos = g_rowptr[d] + atomicAdd(&g_fill[d], 1);
    g_col[pos] = s;
    g_w[pos] = g_dinv[s] * g_dinv[d];
}

// =====================================================================
// bf16-split tensor GEMM: C = epi(A[M,K] @ B[K,N] + bias)
// A fp32 split on the fly; B pre-split (bf16 hi/lo, stride Nb) via cp.async.
// Block 128x128, 8 warps (2m x 4n), warp tile 64x32, BK=16, double buffered.
// (R10's proven occupancy config + R12's proven B-path traffic cut.)
// EPI 0: none  1: relu  2: relu+soft-threshold
// =====================================================================
#define MMA_BF16(d, a0, a1, a2, a3, b0, b1) \
    asm volatile("mma.sync.aligned.m16n8k16.row.col.f32.bf16.bf16.f32 " \
                 "{%0,%1,%2,%3},{%4,%5,%6,%7},{%8,%9},{%0,%1,%2,%3};" \
                 : "+f"(d[0]), "+f"(d[1]), "+f"(d[2]), "+f"(d[3]) \
                 : "r"(a0), "r"(a1), "r"(a2), "r"(a3), "r"(b0), "r"(b1))

__device__ __forceinline__ void ldsm_x4(uint32_t& r0, uint32_t& r1, uint32_t& r2,
                                        uint32_t& r3, uint32_t addr) {
    asm volatile("ldmatrix.sync.aligned.m8n8.x4.shared.b16 {%0,%1,%2,%3},[%4];"
                 : "=r"(r0), "=r"(r1), "=r"(r2), "=r"(r3) : "r"(addr));
}
__device__ __forceinline__ void ldsm_x4_t(uint32_t& r0, uint32_t& r1, uint32_t& r2,
                                          uint32_t& r3, uint32_t addr) {
    asm volatile("ldmatrix.sync.aligned.m8n8.x4.trans.shared.b16 {%0,%1,%2,%3},[%4];"
                 : "=r"(r0), "=r"(r1), "=r"(r2), "=r"(r3) : "r"(addr));
}
__device__ __forceinline__ void cp16(uint32_t dst, const void* src, int bytes) {
    asm volatile("cp.async.cg.shared.global [%0], [%1], 16, %2;"
                 :: "r"(dst), "l"(src), "r"(bytes));
}
#define CP_COMMIT() asm volatile("cp.async.commit_group;" ::: "memory")
#define CP_WAIT0()  asm volatile("cp.async.wait_group 0;" ::: "memory")

template <int EPI>
__global__ __launch_bounds__(256, 2) void k_tgemm(
    const float* __restrict__ A,
    const __nv_bfloat16* __restrict__ Bhi, const __nv_bfloat16* __restrict__ Blo,
    int Nb,   // padded stride of Bhi/Blo
    const float* __restrict__ bias, float* __restrict__ C,
    int M, int K, int N, const float* __restrict__ thrp)
{
    const int PA = 24;    // A pitch (bf16)
    const int PBN = 136;  // B pitch (bf16)
    __shared__ __align__(16) __nv_bfloat16 As_hi[2][128][PA];
    __shared__ __align__(16) __nv_bfloat16 As_lo[2][128][PA];
    __shared__ __align__(16) __nv_bfloat16 Bs_hi[2][16][PBN];
    __shared__ __align__(16) __nv_bfloat16 Bs_lo[2][16][PBN];

    int tid = threadIdx.x;
    int lane = tid & 31, warp = tid >> 5;   // 8 warps
    int wm = warp >> 2;        // 0..1  (64 rows)
    int wn = warp & 3;         // 0..3  (32 cols)
    int fr = lane >> 2;        // 0..7
    int fc = lane & 3;         // 0..3
    int m0 = blockIdx.y * 128, n0 = blockIdx.x * 128;

    // A loader: thread -> row tid>>1, 8 consecutive k at (tid&1)*8
    int arow = tid >> 1;
    int aks  = (tid & 1) * 8;

    // ldmatrix lane addressing (identical mapping to R10's passing kernel)
    int a_r = (lane & 15);
    int a_c = (lane >> 4) * 8;
    int b_k = (lane & 7) + ((lane >> 3) & 1) * 8;
    int b_c = (lane >> 4) * 8;

    uint32_t sAhi = (uint32_t)__cvta_generic_to_shared(&As_hi[0][0][0]);
    uint32_t sAlo = (uint32_t)__cvta_generic_to_shared(&As_lo[0][0][0]);
    uint32_t sBhi = (uint32_t)__cvta_generic_to_shared(&Bs_hi[0][0][0]);
    uint32_t sBlo = (uint32_t)__cvta_generic_to_shared(&Bs_lo[0][0][0]);

    float acc[4][4][4];
#pragma unroll
    for (int mi = 0; mi < 4; mi++)
#pragma unroll
        for (int ni = 0; ni < 4; ni++)
#pragma unroll
            for (int q = 0; q < 4; q++) acc[mi][ni][q] = 0.f;

    float fa[8];
    int nch = CDIV(K, 16);

#define LDG_CHUNK(kc) do { \
    int k0_ = (kc) * 16; \
    long long ar_ = m0 + arow; \
    const float* pA_ = A + (size_t)ar_ * K + k0_ + aks; \
    bool rok_ = ar_ < M; \
    _Pragma("unroll") \
    for (int j = 0; j < 8; j++) { \
        int k_ = k0_ + aks + j; \
        fa[j] = (rok_ && k_ < K) ? pA_[j] : 0.f; \
    } \
} while (0)

// cp.async B chunk kc into buffer b (hi + lo). 256 thr x 1 slot of 16B per array.
#define CPB_CHUNK(kc, b) do { \
    int k0_ = (kc) * 16; \
    int kr_ = tid >> 4, nc_ = (tid & 15) * 8; \
    int kg_ = k0_ + kr_; \
    int rem_ = (Nb - (n0 + nc_)) * 2; \
    int val_ = (kg_ < K) ? (rem_ < 0 ? 0 : (rem_ > 16 ? 16 : rem_)) : 0; \
    size_t go_ = (size_t)kg_ * Nb + n0 + nc_; \
    uint32_t so_ = (uint32_t)((((b) * 16 + kr_) * PBN + nc_) * 2); \
    cp16(sBhi + so_, Bhi + go_, val_); \
    cp16(sBlo + so_, Blo + go_, val_); \
} while (0)

#define STS_CHUNK(b) do { \
    _Pragma("unroll") \
    for (int i = 0; i < 4; i++) { \
        float v0_ = fa[2 * i], v1_ = fa[2 * i + 1]; \
        __nv_bfloat16 h0_ = __float2bfloat16(v0_); \
        __nv_bfloat16 h1_ = __float2bfloat16(v1_); \
        __nv_bfloat16 l0_ = __float2bfloat16(v0_ - __bfloat162float(h0_)); \
        __nv_bfloat16 l1_ = __float2bfloat16(v1_ - __bfloat162float(h1_)); \
        __nv_bfloat162 hh_; hh_.x = h0_; hh_.y = h1_; \
        __nv_bfloat162 ll_; ll_.x = l0_; ll_.y = l1_; \
        *(__nv_bfloat162*)&As_hi[b][arow][aks + 2 * i] = hh_; \
        *(__nv_bfloat162*)&As_lo[b][arow][aks + 2 * i] = ll_; \
    } \
} while (0)

    // prologue
    CPB_CHUNK(0, 0);
    CP_COMMIT();
    LDG_CHUNK(0);
    STS_CHUNK(0);
    CP_WAIT0();
    __syncthreads();

    int buf = 0;
    for (int ch = 0; ch < nch; ch++) {
        bool more = (ch + 1) < nch;
        if (more) {
            LDG_CHUNK(ch + 1);
            CPB_CHUNK(ch + 1, buf ^ 1);
            CP_COMMIT();
        }

        // A fragments (hi+lo): 8 LDSM.x4 per warp
        uint32_t ah[4][4], al[4][4];
#pragma unroll
        for (int mi = 0; mi < 4; mi++) {
            uint32_t off = (uint32_t)(((buf * 128 + wm * 64 + mi * 16 + a_r) * PA + a_c) * 2);
            ldsm_x4(ah[mi][0], ah[mi][1], ah[mi][2], ah[mi][3], sAhi + off);
            ldsm_x4(al[mi][0], al[mi][1], al[mi][2], al[mi][3], sAlo + off);
        }
        // B fragments: 2 pairs of 16 cols (warp covers 32 cols)
#pragma unroll
        for (int p = 0; p < 2; p++) {
            int c0 = wn * 32 + p * 16;
            uint32_t off = (uint32_t)(((buf * 16 + b_k) * PBN + c0 + b_c) * 2);
            uint32_t bh0, bh1, bh2, bh3, bl0, bl1, bl2, bl3;
            ldsm_x4_t(bh0, bh1, bh2, bh3, sBhi + off);
            ldsm_x4_t(bl0, bl1, bl2, bl3, sBlo + off);
#pragma unroll
            for (int mi = 0; mi < 4; mi++) {
                MMA_BF16(acc[mi][2 * p], ah[mi][0], ah[mi][1], ah[mi][2], ah[mi][3], bh0, bh1);
                MMA_BF16(acc[mi][2 * p], ah[mi][0], ah[mi][1], ah[mi][2], ah[mi][3], bl0, bl1);
                MMA_BF16(acc[mi][2 * p], al[mi][0], al[mi][1], al[mi][2], al[mi][3], bh0, bh1);
                MMA_BF16(acc[mi][2 * p + 1], ah[mi][0], ah[mi][1], ah[mi][2], ah[mi][3], bh2, bh3);
                MMA_BF16(acc[mi][2 * p + 1], ah[mi][0], ah[mi][1], ah[mi][2], ah[mi][3], bl2, bl3);
                MMA_BF16(acc[mi][2 * p + 1], al[mi][0], al[mi][1], al[mi][2], al[mi][3], bh2, bh3);
            }
        }

        if (more) STS_CHUNK(buf ^ 1);
        CP_WAIT0();
        __syncthreads();
        buf ^= 1;
    }

    float thr = (EPI == 2) ? *thrp : 0.f;
#pragma unroll
    for (int mi = 0; mi < 4; mi++) {
#pragma unroll
        for (int ni = 0; ni < 4; ni++) {
            int r0 = m0 + wm * 64 + mi * 16 + fr;
            int c0 = n0 + wn * 32 + ni * 8 + fc * 2;
#pragma unroll
            for (int q = 0; q < 4; q++) {
                int r = r0 + (q >> 1) * 8;
                int c = c0 + (q & 1);
                if (r < M && c < N) {
                    float z = acc[mi][ni][q];
                    if (bias) z += bias[c];
                    if (EPI == 1) z = fmaxf(z, 0.f);
                    if (EPI == 2) z = fmaxf(z - thr, 0.f);
                    C[(size_t)r * N + c] = z;
                }
            }
        }
    }
#undef LDG_CHUNK
#undef CPB_CHUNK
#undef STS_CHUNK
}

// ---------------- GCN aggregation ----------------
template <int F>
__global__ void k_agg(const float* __restrict__ t, const float* __restrict__ bias,
                      float* __restrict__ h)
{
    int node = blockIdx.x;
    int f = threadIdx.x;
    float di = g_dinv[node];
    float acc = di * di * t[(size_t)node * F + f];
    int beg = g_rowptr[node], end = g_rowptr[node + 1];
    __shared__ int scol[128];
    __shared__ float sw[128];
    for (int base = beg; base < end; base += 128) {
        int nchunk = min(128, end - base);
        __syncthreads();
        if (f < nchunk) { scol[f] = g_col[base + f]; sw[f] = g_w[base + f]; }
        __syncthreads();
        for (int j = 0; j < nchunk; j++)
            acc += sw[j] * t[(size_t)scol[j] * F + f];
    }
    float z = acc + bias[f];
    h[(size_t)node * F + f] = (z > 0.f) ? z : expm1f(z);
}

// ---------------- pair gather + L2 normalize ----------------
__global__ void k_pairs(const float* __restrict__ h, const void* i1, const void* i2) {
    int b = blockIdx.x;
    int k = threadIdx.x;  // 128
    int a1 = ld_idx(i1, b), a2 = ld_idx(i2, b);
    float v1 = h[(size_t)a1 * 128 + k];
    float v2 = h[(size_t)a2 * 128 + k];
    float s = v1 * v1 + v2 * v2;
    __shared__ float red[4];
#pragma unroll
    for (int o = 16; o; o >>= 1) s += __shfl_down_sync(0xffffffffu, s, o);
    if ((k & 31) == 0) red[k >> 5] = s;
    __syncthreads();
    float tot = red[0] + red[1] + red[2] + red[3];
    float nrm = fmaxf(sqrtf(tot), 1e-12f);
    float inv = 1.f / nrm;
    g_xc[(size_t)b * 256 + k] = v1 * inv;
    g_xc[(size_t)b * 256 + 128 + k] = v2 * inv;
}

// ---------------- final 64->2 linear ----------------
__global__ void k_out(const float* __restrict__ W, const float* __restrict__ bias,
                      float* __restrict__ out) {
    int b = blockIdx.x;
    int lane = threadIdx.x;  // 32
    float a0 = 0.f, a1 = 0.f;
    for (int k = lane; k < 64; k += 32) {
        float v = g_p3[(size_t)b * 64 + k];
        a0 += v * W[k * 2 + 0];
        a1 += v * W[k * 2 + 1];
    }
#pragma unroll
    for (int o = 16; o; o >>= 1) {
        a0 += __shfl_down_sync(0xffffffffu, a0, o);
        a1 += __shfl_down_sync(0xffffffffu, a1, o);
    }
    if (lane == 0) {
        out[b * 2 + 0] = a0 + bias[0];
        out[b * 2 + 1] = a1 + bias[1];
    }
}

// ---------------- launch ----------------
extern "C" void kernel_launch(void* const* d_in, const int* in_sizes, int n_in,
                              void* d_out, int out_size)
{
    const float* cid   = (const float*)d_in[0];
    const void*  edges = d_in[1];
    const void*  i1    = d_in[2];
    const void*  i2    = d_in[3];
    const float* thr   = (const float*)d_in[4];
    const float* bbW2  = (const float*)d_in[5];
    const float* bbb2  = (const float*)d_in[6];
    const float* bbW3  = (const float*)d_in[7];
    const float* bbb3  = (const float*)d_in[8];
    const float* gW[5] = {(const float*)d_in[9],  (const float*)d_in[11],
                          (const float*)d_in[13], (const float*)d_in[15],
                          (const float*)d_in[17]};
    const float* gb[5] = {(const float*)d_in[10], (const float*)d_in[12],
                          (const float*)d_in[14], (const float*)d_in[16],
                          (const float*)d_in[18]};
    const float* fc1W = (const float*)d_in[19];
    const float* fc1b = (const float*)d_in[20];
    const float* fc2W = (const float*)d_in[21];
    const float* fc2b = (const float*)d_in[22];
    const float* fc3W = (const float*)d_in[23];
    const float* fc3b = (const float*)d_in[24];
    const float* oW   = (const float*)d_in[25];
    const float* ob   = (const float*)d_in[26];
    float* out = (float*)d_out;

    float *x881, *h, *t, *xc, *p1, *p3;
    cudaGetSymbolAddress((void**)&x881, g_x881);
    cudaGetSymbolAddress((void**)&h,    g_h);
    cudaGetSymbolAddress((void**)&t,    g_t);
    cudaGetSymbolAddress((void**)&xc,   g_xc);
    cudaGetSymbolAddress((void**)&p1,   g_p1);
    cudaGetSymbolAddress((void**)&p3,   g_p3);
    __nv_bfloat16 *whi, *wlo;
    cudaGetSymbolAddress((void**)&whi, g_whi);
    cudaGetSymbolAddress((void**)&wlo, g_wlo);

    // split W2 first, keep big GEMM at profiled launch slot #4
    k_split<<<CDIV(881 * 888, 256), 256>>>(bbW2, 881, 881, 888, O_W2);
    k_init<<<CDIV(N_NODES, 256), 256>>>((const unsigned int*)edges);
    k_count<<<CDIV(N_EDGES, 256), 256>>>(edges);
    k_tgemm<2><<<dim3(CDIV(881, 128), CDIV(N_NODES, 128)), 256>>>(
        cid, whi + O_W2, wlo + O_W2, 888, bbb2, x881, N_NODES, 881, 881, thr);
    k_dinv<<<CDIV(N_NODES, 256), 256>>>();
    k_scan<<<1, 1024>>>();
    k_fill<<<CDIV(N_EDGES, 256), 256>>>(edges);

    // split remaining weights
    k_split<<<CDIV(881 * 256, 256), 256>>>(bbW3, 881, 256, 256, O_W3);
    k_split<<<CDIV(256 * 256, 256), 256>>>(gW[0], 256, 256, 256, O_G1);
    k_split<<<CDIV(256 * 256, 256), 256>>>(gW[1], 256, 256, 256, O_G2);
    k_split<<<CDIV(256 * 256, 256), 256>>>(gW[2], 256, 256, 256, O_G3);
    k_split<<<CDIV(256 * 128, 256), 256>>>(gW[3], 256, 128, 128, O_G4);
    k_split<<<CDIV(128 * 128, 256), 256>>>(gW[4], 128, 128, 128, O_G5);
    k_split<<<CDIV(256 * 1024, 256), 256>>>(fc1W, 256, 1024, 1024, O_F1);
    k_split<<<CDIV(1024 * 256, 256), 256>>>(fc2W, 1024, 256, 256, O_F2);
    k_split<<<CDIV(256 * 64, 256), 256>>>(fc3W, 256, 64, 64, O_F3);

    k_tgemm<1><<<dim3(CDIV(256, 128), CDIV(N_NODES, 128)), 256>>>(
        x881, whi + O_W3, wlo + O_W3, 256, bbb3, h, N_NODES, 881, 256, nullptr);

    // 5 GCN layers
    const int fin[5]  = {256, 256, 256, 256, 128};
    const int fout[5] = {256, 256, 256, 128, 128};
    const int goff[5] = {O_G1, O_G2, O_G3, O_G4, O_G5};
    for (int l = 0; l < 5; l++) {
        k_tgemm<0><<<dim3(CDIV(fout[l], 128), CDIV(N_NODES, 128)), 256>>>(
            h, whi + goff[l], wlo + goff[l], fout[l], nullptr, t,
            N_NODES, fin[l], fout[l], nullptr);
        if (fout[l] == 256)
            k_agg<256><<<N_NODES, 256>>>(t, gb[l], h);
        else
            k_agg<128><<<N_NODES, 128>>>(t, gb[l], h);
    }

    // pair readout
    k_pairs<<<B_PAIRS, 128>>>(h, i1, i2);
    k_tgemm<1><<<dim3(CDIV(1024, 128), CDIV(B_PAIRS, 128)), 256>>>(
        xc, whi + O_F1, wlo + O_F1, 1024, fc1b, p1, B_PAIRS, 256, 1024, nullptr);
    k_tgemm<1><<<dim3(CDIV(256, 128), CDIV(B_PAIRS, 128)), 256>>>(
        p1, whi + O_F2, wlo + O_F2, 256, fc2b, xc, B_PAIRS, 1024, 256, nullptr);
    k_tgemm<1><<<dim3(CDIV(64, 128), CDIV(B_PAIRS, 128)), 256>>>(
        xc, whi + O_F3, wlo + O_F3, 64, fc3b, p3, B_PAIRS, 256, 64, nullptr);
    k_out<<<B_PAIRS, 32>>>(oW, ob, out);
}